// round 5
// baseline (speedup 1.0000x reference)
#include <cuda_runtime.h>
#include <cuda_fp16.h>
#include <cstdint>

// ---------------- problem constants ----------------
#define N_ROWS 16384
#define DF     128
#define KC     32                 // K chunk per ring stage
#define NITER  (N_ROWS / KC)      // 512
#define NSTG   6                  // A-ring depth

// XW in mma-B fragment order: [chunk c][n-half h][lane lid][32 u32]
//   u32 index = ks*16 + ni*2 + which, value = half2{XW[2kk][n], XW[2kk+1][n]}
//   kk = ks*8 + (which? tg+4 : tg), n = h*64 + ni*8 + g, lid = 4g+tg
__device__ uint32_t g_XWf[(size_t)NITER * 2048];   // 4 MiB

__device__ __forceinline__ uint32_t packh2(float lo, float hi) {
    __half2 h = __floats2half2_rn(lo, hi);
    return *(uint32_t*)&h;
}
__device__ __forceinline__ uint32_t smem_u32(const void* p) {
    uint32_t a;
    asm("{ .reg .u64 t; cvta.to.shared.u64 t, %1; cvt.u32.u64 %0, t; }" : "=r"(a) : "l"(p));
    return a;
}
__device__ __forceinline__ void bar_sync_named(int id) {
    asm volatile("bar.sync %0, 512;" :: "r"(id) : "memory");
}
__device__ __forceinline__ void bar_arrive_named(int id) {
    asm volatile("bar.arrive %0, 512;" :: "r"(id) : "memory");
}
// barrier ids: FULL(s) = 1+s (1..6), EMPTY(s) = 7+s (7..12); id 0 = __syncthreads

__device__ __forceinline__ size_t xwf_idx(int p, int n) {
    int c = p >> 4, kk = p & 15;
    int ks = kk >> 3, which = (kk >> 2) & 1, tg = kk & 3;
    int h = n >> 6, g = n & 7, ni = (n >> 3) & 7;
    int lid = 4 * g + tg;
    return ((size_t)(c * 2 + h) * 32 + lid) * 32 + ks * 16 + ni * 2 + which;
}

// ---------------- kernel 1: XW = x @ W, stored fragment-ordered ----------------
#define XW_SMEM ((128 * 132 + 128 * 128) * 4)

__global__ void __launch_bounds__(256) xw_kernel(const float* __restrict__ x,
                                                 const float* __restrict__ W) {
    extern __shared__ float sm_xw[];
    float* xsT = sm_xw;              // [128][132] transposed x tile
    float* Ws  = sm_xw + 128 * 132;  // [128][128]
    const int tid = threadIdx.x;
    const int j0 = blockIdx.x * 128;

    for (int idx = tid; idx < 128 * 128; idx += 256) {
        int j = idx >> 7, k = idx & 127;
        xsT[k * 132 + j] = x[(size_t)(j0 + j) * DF + k];
        Ws[idx] = W[idx];
    }
    __syncthreads();

    const int tx = tid & 15, ty = tid >> 4;
    const int jb = ty * 8, db = tx * 8;
    float acc[8][8];
#pragma unroll
    for (int a = 0; a < 8; a++)
#pragma unroll
        for (int b = 0; b < 8; b++) acc[a][b] = 0.0f;

    for (int k = 0; k < 128; k++) {
        float4 a0 = *(const float4*)(xsT + k * 132 + jb);
        float4 a1 = *(const float4*)(xsT + k * 132 + jb + 4);
        float4 b0 = *(const float4*)(Ws + k * 128 + db);
        float4 b1 = *(const float4*)(Ws + k * 128 + db + 4);
        float aa[8] = {a0.x, a0.y, a0.z, a0.w, a1.x, a1.y, a1.z, a1.w};
        float bb[8] = {b0.x, b0.y, b0.z, b0.w, b1.x, b1.y, b1.z, b1.w};
#pragma unroll
        for (int jj = 0; jj < 8; jj++)
#pragma unroll
            for (int dd = 0; dd < 8; dd++) acc[jj][dd] += aa[jj] * bb[dd];
    }

    const int jp = (j0 + jb) >> 1;   // global pair row of q=0
#pragma unroll
    for (int q = 0; q < 4; q++) {
#pragma unroll
        for (int dd = 0; dd < 8; dd++) {
            g_XWf[xwf_idx(jp + q, db + dd)] = packh2(acc[2 * q][dd], acc[2 * q + 1][dd]);
        }
    }
}

// ---------------- kernel 2: warp-specialized fused exp + softmax-GEMM ----------------
// 512 threads: tid<256 consumers (8 mma warps), tid>=256 producers (A path only).
// A ring: 6 stages x [128 rows x 20 u32] fp16-pairs.
#define SA2 20
#define A_STG_B  (128 * SA2 * 4)                 // 10240
#define A_OFF    0u
#define RS_OFF   (A_OFF + NSTG * A_STG_B)        // 61440
#define BIAS_OFF (RS_OFF + 512)                  // 61952
#define FUSED_SMEM (BIAS_OFF + 512)              // 62464

__global__ void __launch_bounds__(512, 1) fused_kernel(const float* __restrict__ adj,
                                                       const float* __restrict__ bias,
                                                       float* __restrict__ out) {
    extern __shared__ char sm8[];
    float* rs = (float*)(sm8 + RS_OFF);
    float* bs = (float*)(sm8 + BIAS_OFF);

    const int tid = threadIdx.x;
    const int m0 = blockIdx.x * 128;

    if (tid < DF) bs[tid] = bias[tid];

    if (tid >= 256) {
        // ================= PRODUCERS (A path) =================
        const int ptid = tid - 256;
        const int r = ptid >> 1;           // adj row within tile
        const int hf = ptid & 1;           // 16-float half of 32-col chunk
        const float* agsrc = adj + (size_t)(m0 + r) * N_ROWS + hf * 16;
        const uint32_t a_sts = (uint32_t)r * SA2 + hf * 8;   // u32 units

        float4 a0b[4], a1b[4];
        float rsum = 0.0f;

#define LDGA(cn, BUF) do {                                                       \
            const float* _p = agsrc + (size_t)(cn) * KC;                         \
            BUF[0] = *(const float4*)(_p);                                       \
            BUF[1] = *(const float4*)(_p + 4);                                   \
            BUF[2] = *(const float4*)(_p + 8);                                   \
            BUF[3] = *(const float4*)(_p + 12);                                  \
        } while (0)

#define PBODY(cn, BUF, S) do {                                                   \
            if ((cn) >= NSTG) bar_sync_named(7 + (S));                           \
            uint32_t pk[8];                                                      \
            _Pragma("unroll")                                                    \
            for (int q = 0; q < 4; q++) {                                        \
                float e0 = __expf(BUF[q].x), e1 = __expf(BUF[q].y);              \
                float e2 = __expf(BUF[q].z), e3 = __expf(BUF[q].w);              \
                rsum += (e0 + e1) + (e2 + e3);                                   \
                pk[2 * q]     = packh2(e0, e1);                                  \
                pk[2 * q + 1] = packh2(e2, e3);                                  \
            }                                                                    \
            uint32_t* As = (uint32_t*)(sm8 + A_OFF + (size_t)(S) * A_STG_B);     \
            *(uint4*)(As + a_sts)     = make_uint4(pk[0], pk[1], pk[2], pk[3]);  \
            *(uint4*)(As + a_sts + 4) = make_uint4(pk[4], pk[5], pk[6], pk[7]);  \
            if ((cn) + 2 < NITER) LDGA((cn) + 2, BUF);                           \
            __threadfence_block();                                               \
            bar_arrive_named(1 + (S));                                           \
        } while (0)

        LDGA(0, a0b);
        LDGA(1, a1b);

        int s = 0;
        for (int cn = 0; cn < NITER; cn += 2) {
            PBODY(cn, a0b, s);
            s = (s == NSTG - 1) ? 0 : s + 1;
            PBODY(cn + 1, a1b, s);
            s = (s == NSTG - 1) ? 0 : s + 1;
        }

        rsum += __shfl_xor_sync(0xffffffffu, rsum, 1);
        if (hf == 0) rs[r] = rsum;
        __syncthreads();
    } else {
        // ================= CONSUMERS =================
        const int wid = tid >> 5;
        const int lid = tid & 31;
        const int g = lid >> 2, tg = lid & 3;
        const int mB = (wid & 3) * 32;
        const int h  = wid >> 2;           // n-half
        const int nB = h * 64;

        // B fragment base for this (h, lid); chunk stride = 512 uint4
        const uint4* bptr = (const uint4*)(g_XWf) + ((size_t)h * 32 + lid) * 8;

        uint4 bq[2][4];
#define LDB(c, ks) do {                                                          \
            const uint4* _p = bptr + (size_t)(c) * 512 + (ks) * 4;               \
            bq[ks][0] = __ldg(_p);                                               \
            bq[ks][1] = __ldg(_p + 1);                                           \
            bq[ks][2] = __ldg(_p + 2);                                           \
            bq[ks][3] = __ldg(_p + 3);                                           \
        } while (0)

        float acc[2][8][4];
#pragma unroll
        for (int i = 0; i < 2; i++)
#pragma unroll
            for (int j = 0; j < 8; j++)
#pragma unroll
                for (int c = 0; c < 4; c++) acc[i][j][c] = 0.0f;

        LDB(0, 0);
        LDB(0, 1);

        int s = 0;
        for (int it = 0; it < NITER; ++it) {
            bar_sync_named(1 + s);
            const uint32_t* As = (const uint32_t*)(sm8 + A_OFF + (size_t)s * A_STG_B);
            const int cnx = (it + 1 < NITER) ? it + 1 : it;

#pragma unroll
            for (int ks = 0; ks < 2; ks++) {
                uint32_t af[2][4];
#pragma unroll
                for (int mi = 0; mi < 2; mi++) {
                    const uint32_t* Ar = As + (mB + mi * 16 + g) * SA2 + ks * 8 + tg;
                    af[mi][0] = Ar[0];
                    af[mi][1] = Ar[8 * SA2];
                    af[mi][2] = Ar[4];
                    af[mi][3] = Ar[8 * SA2 + 4];
                }
#pragma unroll
                for (int ni = 0; ni < 8; ni++) {
                    const uint4 u = bq[ks][ni >> 1];
                    const uint32_t b0 = (ni & 1) ? u.z : u.x;
                    const uint32_t b1 = (ni & 1) ? u.w : u.y;
#pragma unroll
                    for (int mi = 0; mi < 2; mi++) {
                        asm volatile(
                            "mma.sync.aligned.m16n8k16.row.col.f32.f16.f16.f32 "
                            "{%0,%1,%2,%3}, {%4,%5,%6,%7}, {%8,%9}, {%0,%1,%2,%3};"
                            : "+f"(acc[mi][ni][0]), "+f"(acc[mi][ni][1]),
                              "+f"(acc[mi][ni][2]), "+f"(acc[mi][ni][3])
                            : "r"(af[mi][0]), "r"(af[mi][1]), "r"(af[mi][2]), "r"(af[mi][3]),
                              "r"(b0), "r"(b1));
                    }
                }
                LDB(cnx, ks);   // refill this ks-half for next chunk
            }

            bar_arrive_named(7 + s);
            s = (s == NSTG - 1) ? 0 : s + 1;
        }

        __syncthreads();   // rowsums + bias visible

        // epilogue: divide + bias + store
#pragma unroll
        for (int mi = 0; mi < 2; mi++) {
            const int r0 = mB + mi * 16 + g;
            const int r1 = r0 + 8;
            const float inv0 = 1.0f / rs[r0];
            const float inv1 = 1.0f / rs[r1];
#pragma unroll
            for (int ni = 0; ni < 8; ni++) {
                const int c = nB + ni * 8 + 2 * tg;
                const float b0v = bs[c];
                const float b1v = bs[c + 1];
                float2 o;
                o.x = acc[mi][ni][0] * inv0 + b0v;
                o.y = acc[mi][ni][1] * inv0 + b1v;
                *(float2*)(out + (size_t)(m0 + r0) * DF + c) = o;
                o.x = acc[mi][ni][2] * inv1 + b0v;
                o.y = acc[mi][ni][3] * inv1 + b1v;
                *(float2*)(out + (size_t)(m0 + r1) * DF + c) = o;
            }
        }
    }
}

// ---------------- launcher ----------------
extern "C" void kernel_launch(void* const* d_in, const int* in_sizes, int n_in,
                              void* d_out, int out_size) {
    const float* x   = (const float*)d_in[0];
    const float* adj = (const float*)d_in[1];
    const float* W   = (const float*)d_in[2];
    const float* b   = (const float*)d_in[3];
    float* out = (float*)d_out;
    (void)in_sizes; (void)n_in; (void)out_size;

    cudaFuncSetAttribute(xw_kernel, cudaFuncAttributeMaxDynamicSharedMemorySize, XW_SMEM);
    cudaFuncSetAttribute(fused_kernel, cudaFuncAttributeMaxDynamicSharedMemorySize, FUSED_SMEM);

    xw_kernel<<<N_ROWS / 128, 256, XW_SMEM>>>(x, W);
    fused_kernel<<<N_ROWS / 128, 512, FUSED_SMEM>>>(adj, b, out);
}

// round 6
// speedup vs baseline: 1.1235x; 1.1235x over previous
#include <cuda_runtime.h>
#include <cuda_fp16.h>
#include <cstdint>

// ---------------- problem constants ----------------
#define N_ROWS 16384
#define DF     128
#define KC     64                  // K chunk per ring stage
#define NITER  (N_ROWS / KC)       // 256
#define NSTG   4                   // ring depth

// g_XWf: XW = x@W as fp16 pairs in mma-B fragment order, warp-contiguous + swizzled.
// chunk c (64 k) occupies 16KB: [h(2)][ksg(4)][bh(2)] blocks of 256 u32.
// within a block: u32 addr = ((8*lane + 4*(ni>>2)) ^ (lane&4)) + (ni&3)
//   lane = 4*g + tg ; value = half2{ XW[2p][n], XW[2p+1][n] }
//   p = c*32 + ksg*8 + bh*4 + tg ; n = h*64 + ni*8 + g
__device__ uint32_t g_XWf[(size_t)NITER * 4096];   // 4 MiB

__device__ __forceinline__ uint32_t packh2(float lo, float hi) {
    __half2 h = __floats2half2_rn(lo, hi);
    return *(uint32_t*)&h;
}
__device__ __forceinline__ uint32_t smem_u32(const void* p) {
    uint32_t a;
    asm("{ .reg .u64 t; cvta.to.shared.u64 t, %1; cvt.u32.u64 %0, t; }" : "=r"(a) : "l"(p));
    return a;
}
__device__ __forceinline__ void cp_async16(uint32_t dst, const void* src) {
    asm volatile("cp.async.cg.shared.global [%0], [%1], 16;" :: "r"(dst), "l"(src));
}
#define CP_COMMIT() asm volatile("cp.async.commit_group;" ::: "memory")
#define CP_WAIT(n)  asm volatile("cp.async.wait_group %0;" :: "n"(n) : "memory")

__device__ __forceinline__ void bar_sync_named(int id) {
    asm volatile("bar.sync %0, 512;" :: "r"(id) : "memory");
}
__device__ __forceinline__ void bar_arrive_named(int id) {
    asm volatile("bar.arrive %0, 512;" :: "r"(id) : "memory");
}
// barrier ids: FULL(s)=1+s (1..4), EMPTY(s)=5+s (5..8)

// ---------------- kernel 1: XW = x @ W, emitted fragment-ordered ----------------
#define XW_SMEM ((128 * 132 + 128 * 128) * 4)   // staging reuses xsT region

__global__ void __launch_bounds__(256) xw_kernel(const float* __restrict__ x,
                                                 const float* __restrict__ W) {
    extern __shared__ float sm_xw[];
    float* xsT = sm_xw;              // [128][132] transposed x tile
    float* Ws  = sm_xw + 128 * 132;  // [128][128]
    uint32_t* stage = (uint32_t*)sm_xw;  // 8192 u32 staging (reused after compute)
    const int tid = threadIdx.x;
    const int j0 = blockIdx.x * 128;

    for (int idx = tid; idx < 128 * 128; idx += 256) {
        int j = idx >> 7, k = idx & 127;
        xsT[k * 132 + j] = x[(size_t)(j0 + j) * DF + k];
        Ws[idx] = W[idx];
    }
    __syncthreads();

    const int tx = tid & 15, ty = tid >> 4;
    const int jb = ty * 8, db = tx * 8;
    float acc[8][8];
#pragma unroll
    for (int a = 0; a < 8; a++)
#pragma unroll
        for (int b = 0; b < 8; b++) acc[a][b] = 0.0f;

    for (int k = 0; k < 128; k++) {
        float4 a0 = *(const float4*)(xsT + k * 132 + jb);
        float4 a1 = *(const float4*)(xsT + k * 132 + jb + 4);
        float4 b0 = *(const float4*)(Ws + k * 128 + db);
        float4 b1 = *(const float4*)(Ws + k * 128 + db + 4);
        float aa[8] = {a0.x, a0.y, a0.z, a0.w, a1.x, a1.y, a1.z, a1.w};
        float bb[8] = {b0.x, b0.y, b0.z, b0.w, b1.x, b1.y, b1.z, b1.w};
#pragma unroll
        for (int jj = 0; jj < 8; jj++)
#pragma unroll
            for (int dd = 0; dd < 8; dd++) acc[jj][dd] += aa[jj] * bb[dd];
    }
    __syncthreads();   // done reading xsT/Ws; staging may reuse the space

    // scatter into fragment-order staging (covers 2 chunks = 8192 u32)
#pragma unroll
    for (int q = 0; q < 4; q++) {
        const int p_local = (jb >> 1) + q;          // 0..63
        const int c_local = p_local >> 5;           // 0 or 1
        const int kk = p_local & 31;
        const int ksg = kk >> 3, bh = (kk >> 2) & 1, tg = kk & 3;
#pragma unroll
        for (int dd = 0; dd < 8; dd++) {
            const int n = db + dd;
            const int h = n >> 6, ni = (n >> 3) & 7, g = n & 7;
            const int lane = 4 * g + tg;
            const int off = c_local * 4096 + ((h * 4 + ksg) * 2 + bh) * 256
                          + (((8 * lane + 4 * (ni >> 2)) ^ (lane & 4)) + (ni & 3));
            stage[off] = packh2(acc[2 * q][dd], acc[2 * q + 1][dd]);
        }
    }
    __syncthreads();

    // linear coalesced copy to global
    uint4* dst = (uint4*)(g_XWf + (size_t)blockIdx.x * 8192);
    const uint4* srcv = (const uint4*)stage;
#pragma unroll
    for (int i = 0; i < 8; i++) dst[tid + i * 256] = srcv[tid + i * 256];
}

// ---------------- kernel 2: warp-specialized fused exp + softmax-GEMM ----------------
// 512 threads: tid<256 = MMA consumers (8 warps: 4 m-groups x 2 n-halves),
// tid>=256 = producers (adj LDG -> exp -> A STS; XW via cp.async).
#define SA2 36                                    // A row stride (32 pairs + 4 pad)
#define A_STG_B  (128 * SA2 * 4)                  // 18432
#define B_STG_B  16384
#define A_OFF    0u
#define B_OFF    (A_OFF + NSTG * A_STG_B)         // 73728
#define RS_OFF   (B_OFF + NSTG * B_STG_B)         // 139264
#define BIAS_OFF (RS_OFF + 512)                   // 139776
#define FUSED_SMEM (BIAS_OFF + 512)               // 140288

__global__ void __launch_bounds__(512, 1) fused_kernel(const float* __restrict__ adj,
                                                       const float* __restrict__ bias,
                                                       float* __restrict__ out) {
    extern __shared__ char sm8[];
    const uint32_t sb = smem_u32(sm8);
    float* rs = (float*)(sm8 + RS_OFF);
    float* bs = (float*)(sm8 + BIAS_OFF);

    const int tid = threadIdx.x;
    const int m0 = blockIdx.x * 128;

    if (tid < DF) bs[tid] = bias[tid];

    if (tid >= 256) {
        // ================= PRODUCERS =================
        const int ptid = tid - 256;
        const int r = ptid >> 1;           // adj row within tile
        const int hf = ptid & 1;           // which 32-float half of the 64-col chunk
        const float* agsrc = adj + (size_t)(m0 + r) * N_ROWS + hf * 32;
        // A STS base (u32 units within stage)
        const uint32_t a_sts = (uint32_t)r * SA2 + hf * 16;
        // B cp.async: linear copy, thread covers 4 x 16B
        const uint32_t b_dst0 = sb + B_OFF + (uint32_t)ptid * 16;
        const uint32_t* bgsrc = g_XWf + (size_t)ptid * 4;

        float4 b0buf[8], b1buf[8];
        float rsum = 0.0f;

#define LDGA(cn, BUF) do {                                                        \
            const float* _p = agsrc + (size_t)(cn) * KC;                          \
            _Pragma("unroll")                                                     \
            for (int _q = 0; _q < 8; _q++) BUF[_q] = *(const float4*)(_p + _q*4); \
        } while (0)

#define CPB(cn) do {                                                              \
            const uint32_t* _s = bgsrc + (size_t)(cn) * 4096;                     \
            const uint32_t _d = b_dst0 + (uint32_t)((cn) & 3) * B_STG_B;          \
            cp_async16(_d,         _s);                                           \
            cp_async16(_d + 4096,  _s + 1024);                                    \
            cp_async16(_d + 8192,  _s + 2048);                                    \
            cp_async16(_d + 12288, _s + 3072);                                    \
            CP_COMMIT();                                                          \
        } while (0)

#define PBODY(cn, BUF) do {                                                       \
            if ((cn) + 1 < NITER) {                                               \
                if ((cn) + 1 >= NSTG) bar_sync_named(5 + (((cn) + 1) & 3));       \
                CPB((cn) + 1);                                                    \
            }                                                                     \
            uint32_t pk[16];                                                      \
            _Pragma("unroll")                                                     \
            for (int _q = 0; _q < 8; _q++) {                                      \
                float e0 = __expf(BUF[_q].x), e1 = __expf(BUF[_q].y);             \
                float e2 = __expf(BUF[_q].z), e3 = __expf(BUF[_q].w);             \
                rsum += (e0 + e1) + (e2 + e3);                                    \
                pk[2 * _q]     = packh2(e0, e1);                                  \
                pk[2 * _q + 1] = packh2(e2, e3);                                  \
            }                                                                     \
            uint32_t* As = (uint32_t*)(sm8 + A_OFF + (size_t)((cn) & 3) * A_STG_B) + a_sts; \
            *(uint4*)(As)      = make_uint4(pk[0],  pk[1],  pk[2],  pk[3]);       \
            *(uint4*)(As + 4)  = make_uint4(pk[4],  pk[5],  pk[6],  pk[7]);       \
            *(uint4*)(As + 8)  = make_uint4(pk[8],  pk[9],  pk[10], pk[11]);      \
            *(uint4*)(As + 12) = make_uint4(pk[12], pk[13], pk[14], pk[15]);      \
            if ((cn) + 2 < NITER) LDGA((cn) + 2, BUF);                            \
            if ((cn) + 1 < NITER) { CP_WAIT(1); } else { CP_WAIT(0); }            \
            __threadfence_block();                                                \
            bar_arrive_named(1 + ((cn) & 3));                                     \
        } while (0)

        LDGA(0, b0buf);
        LDGA(1, b1buf);
        CPB(0);

        for (int cn = 0; cn < NITER; cn += 2) {
            PBODY(cn, b0buf);
            PBODY(cn + 1, b1buf);
        }

        rsum += __shfl_xor_sync(0xffffffffu, rsum, 1);
        if (hf == 0) rs[r] = rsum;
        __syncthreads();
    } else {
        // ================= CONSUMERS =================
        const int wid = tid >> 5;
        const int lid = tid & 31;
        const int g = lid >> 2, tg = lid & 3;
        const int mB = (wid & 3) * 32;
        const int h  = wid >> 2;
        const int nB = h * 64;

        // swizzled B LDS offsets (u32 units within a 256-u32 block)
        const uint32_t swz_lo = (uint32_t)((8 * lid) ^ (lid & 4));       // ni 0..3
        const uint32_t swz_hi = (uint32_t)(((8 * lid) + 4) ^ (lid & 4)); // ni 4..7

        float acc[2][8][4];
#pragma unroll
        for (int i = 0; i < 2; i++)
#pragma unroll
            for (int j = 0; j < 8; j++)
#pragma unroll
                for (int c = 0; c < 4; c++) acc[i][j][c] = 0.0f;

        for (int it = 0; it < NITER; ++it) {
            const int s = it & 3;
            bar_sync_named(1 + s);

            const uint32_t* As = (const uint32_t*)(sm8 + A_OFF + (size_t)s * A_STG_B);
            const uint32_t* Bh = (const uint32_t*)(sm8 + B_OFF + (size_t)s * B_STG_B) + h * 2048;

#pragma unroll
            for (int ksg = 0; ksg < 4; ksg++) {
                // A fragments (scalar LDS, conflict-free via SA2=36)
                uint32_t af[2][4];
#pragma unroll
                for (int mi = 0; mi < 2; mi++) {
                    const uint32_t* Ar = As + (mB + mi * 16 + g) * SA2 + ksg * 8 + tg;
                    af[mi][0] = Ar[0];
                    af[mi][1] = Ar[8 * SA2];
                    af[mi][2] = Ar[4];
                    af[mi][3] = Ar[8 * SA2 + 4];
                }
                // B fragments: 4 conflict-free LDS.128
                const uint32_t* Bb = Bh + ksg * 512;
                const uint4 lo0 = *(const uint4*)(Bb + swz_lo);          // b0, ni 0..3
                const uint4 lo1 = *(const uint4*)(Bb + swz_hi);          // b0, ni 4..7
                const uint4 hi0 = *(const uint4*)(Bb + 256 + swz_lo);    // b1, ni 0..3
                const uint4 hi1 = *(const uint4*)(Bb + 256 + swz_hi);    // b1, ni 4..7
                const uint32_t b0a[8] = {lo0.x, lo0.y, lo0.z, lo0.w, lo1.x, lo1.y, lo1.z, lo1.w};
                const uint32_t b1a[8] = {hi0.x, hi0.y, hi0.z, hi0.w, hi1.x, hi1.y, hi1.z, hi1.w};
#pragma unroll
                for (int ni = 0; ni < 8; ni++) {
#pragma unroll
                    for (int mi = 0; mi < 2; mi++) {
                        asm volatile(
                            "mma.sync.aligned.m16n8k16.row.col.f32.f16.f16.f32 "
                            "{%0,%1,%2,%3}, {%4,%5,%6,%7}, {%8,%9}, {%0,%1,%2,%3};"
                            : "+f"(acc[mi][ni][0]), "+f"(acc[mi][ni][1]),
                              "+f"(acc[mi][ni][2]), "+f"(acc[mi][ni][3])
                            : "r"(af[mi][0]), "r"(af[mi][1]), "r"(af[mi][2]), "r"(af[mi][3]),
                              "r"(b0a[ni]), "r"(b1a[ni]));
                    }
                }
            }
            bar_arrive_named(5 + s);
        }

        __syncthreads();   // rowsums + bias visible

        // epilogue: divide + bias + store
#pragma unroll
        for (int mi = 0; mi < 2; mi++) {
            const int r0 = mB + mi * 16 + g;
            const int r1 = r0 + 8;
            const float inv0 = 1.0f / rs[r0];
            const float inv1 = 1.0f / rs[r1];
#pragma unroll
            for (int ni = 0; ni < 8; ni++) {
                const int c = nB + ni * 8 + 2 * tg;
                const float b0v = bs[c];
                const float b1v = bs[c + 1];
                float2 o;
                o.x = acc[mi][ni][0] * inv0 + b0v;
                o.y = acc[mi][ni][1] * inv0 + b1v;
                *(float2*)(out + (size_t)(m0 + r0) * DF + c) = o;
                o.x = acc[mi][ni][2] * inv1 + b0v;
                o.y = acc[mi][ni][3] * inv1 + b1v;
                *(float2*)(out + (size_t)(m0 + r1) * DF + c) = o;
            }
        }
    }
}

// ---------------- launcher ----------------
extern "C" void kernel_launch(void* const* d_in, const int* in_sizes, int n_in,
                              void* d_out, int out_size) {
    const float* x   = (const float*)d_in[0];
    const float* adj = (const float*)d_in[1];
    const float* W   = (const float*)d_in[2];
    const float* b   = (const float*)d_in[3];
    float* out = (float*)d_out;
    (void)in_sizes; (void)n_in; (void)out_size;

    cudaFuncSetAttribute(xw_kernel, cudaFuncAttributeMaxDynamicSharedMemorySize, XW_SMEM);
    cudaFuncSetAttribute(fused_kernel, cudaFuncAttributeMaxDynamicSharedMemorySize, FUSED_SMEM);

    xw_kernel<<<N_ROWS / 128, 256, XW_SMEM>>>(x, W);
    fused_kernel<<<N_ROWS / 128, 512, FUSED_SMEM>>>(adj, b, out);
}

// round 7
// speedup vs baseline: 1.5381x; 1.3690x over previous
#include <cuda_runtime.h>
#include <cuda_fp16.h>
#include <cstdint>

// ---------------- problem constants ----------------
#define N_ROWS 16384
#define DF     128
#define KC     32                 // K chunk per ring stage
#define NITER  (N_ROWS / KC)      // 512
#define NSTG   6                  // ring depth
#define NTHREADS 384

// XW = x @ W, packed as half2 pairs along j (row j/2 holds {XW[2k][d], XW[2k+1][d]}).
__device__ uint32_t g_XWp[(size_t)(N_ROWS / 2) * DF];   // 4 MiB

__device__ __forceinline__ uint32_t packh2(float lo, float hi) {
    __half2 h = __floats2half2_rn(lo, hi);
    return *(uint32_t*)&h;
}
__device__ __forceinline__ uint32_t smem_u32(const void* p) {
    uint32_t a;
    asm("{ .reg .u64 t; cvta.to.shared.u64 t, %1; cvt.u32.u64 %0, t; }" : "=r"(a) : "l"(p));
    return a;
}
__device__ __forceinline__ void cp_async16(uint32_t dst, const void* src) {
    asm volatile("cp.async.cg.shared.global [%0], [%1], 16;" :: "r"(dst), "l"(src));
}
#define CP_COMMIT() asm volatile("cp.async.commit_group;" ::: "memory")
#define CP_WAIT(n)  asm volatile("cp.async.wait_group %0;" :: "n"(n) : "memory")

__device__ __forceinline__ void bar_sync_named(int id) {
    asm volatile("bar.sync %0, %1;" :: "r"(id), "n"(NTHREADS) : "memory");
}
__device__ __forceinline__ void bar_arrive_named(int id) {
    asm volatile("bar.arrive %0, %1;" :: "r"(id), "n"(NTHREADS) : "memory");
}
// barrier ids: FULL(s)=1+s (1..6), EMPTY(s)=7+s (7..12)

// ---------------- kernel 1: XW = x @ W (fp32 compute, fp16-pair store) ----------------
#define XW_SMEM ((128 * 132 + 128 * 128) * 4)

__global__ void __launch_bounds__(256) xw_kernel(const float* __restrict__ x,
                                                 const float* __restrict__ W) {
    extern __shared__ float sm_xw[];
    float* xsT = sm_xw;              // [128][132] transposed x tile
    float* Ws  = sm_xw + 128 * 132;  // [128][128]
    const int tid = threadIdx.x;
    const int j0 = blockIdx.x * 128;

    for (int idx = tid; idx < 128 * 128; idx += 256) {
        int j = idx >> 7, k = idx & 127;
        xsT[k * 132 + j] = x[(size_t)(j0 + j) * DF + k];
        Ws[idx] = W[idx];
    }
    __syncthreads();

    const int tx = tid & 15, ty = tid >> 4;
    const int jb = ty * 8, db = tx * 8;
    float acc[8][8];
#pragma unroll
    for (int a = 0; a < 8; a++)
#pragma unroll
        for (int b = 0; b < 8; b++) acc[a][b] = 0.0f;

    for (int k = 0; k < 128; k++) {
        float4 a0 = *(const float4*)(xsT + k * 132 + jb);
        float4 a1 = *(const float4*)(xsT + k * 132 + jb + 4);
        float4 b0 = *(const float4*)(Ws + k * 128 + db);
        float4 b1 = *(const float4*)(Ws + k * 128 + db + 4);
        float aa[8] = {a0.x, a0.y, a0.z, a0.w, a1.x, a1.y, a1.z, a1.w};
        float bb[8] = {b0.x, b0.y, b0.z, b0.w, b1.x, b1.y, b1.z, b1.w};
#pragma unroll
        for (int jj = 0; jj < 8; jj++)
#pragma unroll
            for (int dd = 0; dd < 8; dd++) acc[jj][dd] += aa[jj] * bb[dd];
    }

    const uint32_t jp = (uint32_t)((j0 + jb) >> 1);
#pragma unroll
    for (int q = 0; q < 4; q++) {
        uint32_t* dst = g_XWp + (size_t)(jp + q) * DF + db;
        uint4 v0, v1;
        v0.x = packh2(acc[2 * q][0], acc[2 * q + 1][0]);
        v0.y = packh2(acc[2 * q][1], acc[2 * q + 1][1]);
        v0.z = packh2(acc[2 * q][2], acc[2 * q + 1][2]);
        v0.w = packh2(acc[2 * q][3], acc[2 * q + 1][3]);
        v1.x = packh2(acc[2 * q][4], acc[2 * q + 1][4]);
        v1.y = packh2(acc[2 * q][5], acc[2 * q + 1][5]);
        v1.z = packh2(acc[2 * q][6], acc[2 * q + 1][6]);
        v1.w = packh2(acc[2 * q][7], acc[2 * q + 1][7]);
        *(uint4*)dst = v0;
        *(uint4*)(dst + 4) = v1;
    }
}

// ---------------- kernel 2: warp-specialized, 64-row CTAs, 2 CTAs/SM ----------------
// 384 threads: tid<256 = consumers (4 m-warps x 16 rows, 2 n-halves),
//              tid>=256 = producers (128 threads: adj->exp->A STS; XW cp.async).
// Ring: 6 stages x { A: 64x20 u32 (5120B), B: 16x136 u32 (8704B) }.
#define SA2 20
#define SB2 136
#define A_STG_B  (64 * SA2 * 4)                  // 5120
#define B_STG_B  (16 * SB2 * 4)                  // 8704
#define A_OFF    0u
#define B_OFF    (A_OFF + NSTG * A_STG_B)        // 30720
#define RS_OFF   (B_OFF + NSTG * B_STG_B)        // 82944
#define BIAS_OFF (RS_OFF + 256)                  // 83200
#define FUSED_SMEM (BIAS_OFF + 512)              // 83712

__global__ void __launch_bounds__(NTHREADS, 2) fused_kernel(const float* __restrict__ adj,
                                                            const float* __restrict__ bias,
                                                            float* __restrict__ out) {
    extern __shared__ char sm8[];
    const uint32_t sb = smem_u32(sm8);
    float* rs = (float*)(sm8 + RS_OFF);
    float* bs = (float*)(sm8 + BIAS_OFF);

    const int tid = threadIdx.x;
    const int m0 = blockIdx.x * 64;

    if (tid < DF) bs[tid] = bias[tid];

    if (tid >= 256) {
        // ================= PRODUCERS =================
        const int ptid = tid - 256;        // 0..127
        const int r = ptid >> 1;           // adj row within 64-row tile
        const int hf = ptid & 1;           // 16-float half of 32-col chunk
        const float* agsrc = adj + (size_t)(m0 + r) * N_ROWS + hf * 16;
        const uint32_t a_sts = (uint32_t)r * SA2 + hf * 8;   // u32 units

        const int kk = ptid >> 3;          // pair-row (0..15)
        const int nb = ptid & 7;           // 16-u32 col block
        const uint32_t* bgsrc = g_XWp + (size_t)kk * DF + nb * 16;
        const uint32_t b_dst = sb + B_OFF + ((uint32_t)kk * SB2 + nb * 16) * 4;

        float4 a0b[4], a1b[4];
        float rsum = 0.0f;

#define LDGA(cn, BUF) do {                                                       \
            const float* _p = agsrc + (size_t)(cn) * KC;                         \
            BUF[0] = *(const float4*)(_p);                                       \
            BUF[1] = *(const float4*)(_p + 4);                                   \
            BUF[2] = *(const float4*)(_p + 8);                                   \
            BUF[3] = *(const float4*)(_p + 12);                                  \
        } while (0)
#define CPB(cn, S) do {                                                          \
            const uint32_t* _p = bgsrc + (size_t)(cn) * 16 * DF;                 \
            uint32_t _d = b_dst + (uint32_t)(S) * B_STG_B;                       \
            cp_async16(_d,      _p);                                             \
            cp_async16(_d + 16, _p + 4);                                         \
            cp_async16(_d + 32, _p + 8);                                         \
            cp_async16(_d + 48, _p + 12);                                        \
            CP_COMMIT();                                                         \
        } while (0)

        // PBODY(cn): stage S holds chunk cn (its B already in flight / arrived);
        // issues B for chunk cn+1 into SN, exp+STS A(cn), prefetch adj cn+2.
#define PBODY(cn, BUF, S, SN) do {                                               \
            if ((cn) + 1 < NITER) {                                              \
                if ((cn) + 1 >= NSTG) bar_sync_named(7 + (SN));                  \
                CPB((cn) + 1, SN);                                               \
            }                                                                    \
            uint32_t pk[8];                                                      \
            _Pragma("unroll")                                                    \
            for (int q = 0; q < 4; q++) {                                        \
                float e0 = __expf(BUF[q].x), e1 = __expf(BUF[q].y);              \
                float e2 = __expf(BUF[q].z), e3 = __expf(BUF[q].w);              \
                rsum += (e0 + e1) + (e2 + e3);                                   \
                pk[2 * q]     = packh2(e0, e1);                                  \
                pk[2 * q + 1] = packh2(e2, e3);                                  \
            }                                                                    \
            uint32_t* As = (uint32_t*)(sm8 + A_OFF + (size_t)(S) * A_STG_B);     \
            *(uint4*)(As + a_sts)     = make_uint4(pk[0], pk[1], pk[2], pk[3]);  \
            *(uint4*)(As + a_sts + 4) = make_uint4(pk[4], pk[5], pk[6], pk[7]);  \
            if ((cn) + 2 < NITER) LDGA((cn) + 2, BUF);                           \
            if ((cn) + 1 < NITER) { CP_WAIT(1); } else { CP_WAIT(0); }           \
            __threadfence_block();                                               \
            bar_arrive_named(1 + (S));                                           \
        } while (0)

        LDGA(0, a0b);
        LDGA(1, a1b);
        CPB(0, 0);

        int s = 0;
        for (int cn = 0; cn < NITER; cn += 2) {
            const int s1 = (s + 1 == NSTG) ? 0 : s + 1;
            const int s2 = (s1 + 1 == NSTG) ? 0 : s1 + 1;
            PBODY(cn, a0b, s, s1);
            PBODY(cn + 1, a1b, s1, s2);
            s = s2;
        }

        rsum += __shfl_xor_sync(0xffffffffu, rsum, 1);
        if (hf == 0) rs[r] = rsum;
        __syncthreads();
        // producers exit; consumers do epilogue
    } else {
        // ================= CONSUMERS =================
        const int wid = tid >> 5;
        const int lid = tid & 31;
        const int g = lid >> 2, tg = lid & 3;
        const int mB = (wid & 3) * 16;     // 16 rows per m-warp
        const int h  = wid >> 2;           // n-half
        const int nB = h * 64;

        float acc[8][4];
#pragma unroll
        for (int j = 0; j < 8; j++)
#pragma unroll
            for (int c = 0; c < 4; c++) acc[j][c] = 0.0f;

        int s = 0;
        for (int it = 0; it < NITER; ++it) {
            bar_sync_named(1 + s);

            const uint32_t* As = (const uint32_t*)(sm8 + A_OFF + (size_t)s * A_STG_B);
            const uint32_t* Bs = (const uint32_t*)(sm8 + B_OFF + (size_t)s * B_STG_B);
#pragma unroll
            for (int ks = 0; ks < 2; ks++) {
                uint32_t af[4];
                const uint32_t* Ar = As + (mB + g) * SA2 + ks * 8 + tg;
                af[0] = Ar[0];
                af[1] = Ar[8 * SA2];
                af[2] = Ar[4];
                af[3] = Ar[8 * SA2 + 4];
#pragma unroll
                for (int ni = 0; ni < 8; ni++) {
                    const uint32_t* Br = Bs + (ks * 8 + tg) * SB2 + nB + ni * 8 + g;
                    uint32_t b0 = Br[0];
                    uint32_t b1 = Br[4 * SB2];
                    asm volatile(
                        "mma.sync.aligned.m16n8k16.row.col.f32.f16.f16.f32 "
                        "{%0,%1,%2,%3}, {%4,%5,%6,%7}, {%8,%9}, {%0,%1,%2,%3};"
                        : "+f"(acc[ni][0]), "+f"(acc[ni][1]),
                          "+f"(acc[ni][2]), "+f"(acc[ni][3])
                        : "r"(af[0]), "r"(af[1]), "r"(af[2]), "r"(af[3]),
                          "r"(b0), "r"(b1));
                }
            }
            bar_arrive_named(7 + s);
            s = (s + 1 == NSTG) ? 0 : s + 1;
        }

        __syncthreads();   // rowsums + bias visible

        // epilogue: divide + bias + store
        const int r0 = mB + g;
        const int r1 = r0 + 8;
        const float inv0 = 1.0f / rs[r0];
        const float inv1 = 1.0f / rs[r1];
#pragma unroll
        for (int ni = 0; ni < 8; ni++) {
            const int c = nB + ni * 8 + 2 * tg;
            const float b0v = bs[c];
            const float b1v = bs[c + 1];
            float2 o;
            o.x = acc[ni][0] * inv0 + b0v;
            o.y = acc[ni][1] * inv0 + b1v;
            *(float2*)(out + (size_t)(m0 + r0) * DF + c) = o;
            o.x = acc[ni][2] * inv1 + b0v;
            o.y = acc[ni][3] * inv1 + b1v;
            *(float2*)(out + (size_t)(m0 + r1) * DF + c) = o;
        }
    }
}

// ---------------- launcher ----------------
extern "C" void kernel_launch(void* const* d_in, const int* in_sizes, int n_in,
                              void* d_out, int out_size) {
    const float* x   = (const float*)d_in[0];
    const float* adj = (const float*)d_in[1];
    const float* W   = (const float*)d_in[2];
    const float* b   = (const float*)d_in[3];
    float* out = (float*)d_out;
    (void)in_sizes; (void)n_in; (void)out_size;

    cudaFuncSetAttribute(xw_kernel, cudaFuncAttributeMaxDynamicSharedMemorySize, XW_SMEM);
    cudaFuncSetAttribute(fused_kernel, cudaFuncAttributeMaxDynamicSharedMemorySize, FUSED_SMEM);

    xw_kernel<<<N_ROWS / 128, 256, XW_SMEM>>>(x, W);
    fused_kernel<<<N_ROWS / 64, NTHREADS, FUSED_SMEM>>>(adj, b, out);
}

// round 8
// speedup vs baseline: 1.9835x; 1.2896x over previous
#include <cuda_runtime.h>
#include <cuda_fp16.h>
#include <cstdint>

// ---------------- problem constants ----------------
#define N_ROWS 16384
#define DF     128
#define KC     32                 // K chunk per ring stage
#define NITER  (N_ROWS / KC)      // 512
#define NPITER (NITER / 2)        // 256 stage-pairs
#define NPAIR  3                  // ring = 3 pairs = 6 stages

// XW = x @ W, packed as half2 pairs along j (row j/2 holds {XW[2k][d], XW[2k+1][d]}).
__device__ uint32_t g_XWp[(size_t)(N_ROWS / 2) * DF];   // 4 MiB

__device__ __forceinline__ uint32_t packh2(float lo, float hi) {
    __half2 h = __floats2half2_rn(lo, hi);
    return *(uint32_t*)&h;
}
__device__ __forceinline__ uint32_t smem_u32(const void* p) {
    uint32_t a;
    asm("{ .reg .u64 t; cvta.to.shared.u64 t, %1; cvt.u32.u64 %0, t; }" : "=r"(a) : "l"(p));
    return a;
}
__device__ __forceinline__ void cp_async16(uint32_t dst, const void* src) {
    asm volatile("cp.async.cg.shared.global [%0], [%1], 16;" :: "r"(dst), "l"(src));
}
#define CP_COMMIT() asm volatile("cp.async.commit_group;" ::: "memory")
#define CP_WAIT(n)  asm volatile("cp.async.wait_group %0;" :: "n"(n) : "memory")

__device__ __forceinline__ void bar_sync_named(int id) {
    asm volatile("bar.sync %0, 512;" :: "r"(id) : "memory");
}
__device__ __forceinline__ void bar_arrive_named(int id) {
    asm volatile("bar.arrive %0, 512;" :: "r"(id) : "memory");
}
// barrier ids: FULL(p)=1+p (1..3), EMPTY(p)=4+p (4..6)

// ---------------- kernel 1: XW = x @ W (fp32 compute, fp16-pair store) ----------------
#define XW_SMEM ((128 * 132 + 128 * 128) * 4)

__global__ void __launch_bounds__(256) xw_kernel(const float* __restrict__ x,
                                                 const float* __restrict__ W) {
    extern __shared__ float sm_xw[];
    float* xsT = sm_xw;              // [128][132] transposed x tile
    float* Ws  = sm_xw + 128 * 132;  // [128][128]
    const int tid = threadIdx.x;
    const int j0 = blockIdx.x * 128;

    for (int idx = tid; idx < 128 * 128; idx += 256) {
        int j = idx >> 7, k = idx & 127;
        xsT[k * 132 + j] = x[(size_t)(j0 + j) * DF + k];
        Ws[idx] = W[idx];
    }
    __syncthreads();

    const int tx = tid & 15, ty = tid >> 4;
    const int jb = ty * 8, db = tx * 8;
    float acc[8][8];
#pragma unroll
    for (int a = 0; a < 8; a++)
#pragma unroll
        for (int b = 0; b < 8; b++) acc[a][b] = 0.0f;

    for (int k = 0; k < 128; k++) {
        float4 a0 = *(const float4*)(xsT + k * 132 + jb);
        float4 a1 = *(const float4*)(xsT + k * 132 + jb + 4);
        float4 b0 = *(const float4*)(Ws + k * 128 + db);
        float4 b1 = *(const float4*)(Ws + k * 128 + db + 4);
        float aa[8] = {a0.x, a0.y, a0.z, a0.w, a1.x, a1.y, a1.z, a1.w};
        float bb[8] = {b0.x, b0.y, b0.z, b0.w, b1.x, b1.y, b1.z, b1.w};
#pragma unroll
        for (int jj = 0; jj < 8; jj++)
#pragma unroll
            for (int dd = 0; dd < 8; dd++) acc[jj][dd] += aa[jj] * bb[dd];
    }

    const uint32_t jp = (uint32_t)((j0 + jb) >> 1);
#pragma unroll
    for (int q = 0; q < 4; q++) {
        uint32_t* dst = g_XWp + (size_t)(jp + q) * DF + db;
        uint4 v0, v1;
        v0.x = packh2(acc[2 * q][0], acc[2 * q + 1][0]);
        v0.y = packh2(acc[2 * q][1], acc[2 * q + 1][1]);
        v0.z = packh2(acc[2 * q][2], acc[2 * q + 1][2]);
        v0.w = packh2(acc[2 * q][3], acc[2 * q + 1][3]);
        v1.x = packh2(acc[2 * q][4], acc[2 * q + 1][4]);
        v1.y = packh2(acc[2 * q][5], acc[2 * q + 1][5]);
        v1.z = packh2(acc[2 * q][6], acc[2 * q + 1][6]);
        v1.w = packh2(acc[2 * q][7], acc[2 * q + 1][7]);
        *(uint4*)dst = v0;
        *(uint4*)(dst + 4) = v1;
    }
}

// ---------------- kernel 2: warp-specialized fused exp + softmax-GEMM ----------------
// 512 threads: tid<256 = MMA consumers (8 warps), tid>=256 = producers.
// Ring: 6 stages (3 pairs) x { A: 128x20 u32 fp16-pairs (10240B), B: 16x136 u32 (8704B) }.
#define SA2 20
#define SB2 136
#define A_STG_B  (128 * SA2 * 4)                 // 10240
#define B_STG_B  (16 * SB2 * 4)                  // 8704
#define A_OFF    0u
#define B_OFF    (A_OFF + 6 * A_STG_B)           // 61440
#define RS_OFF   (B_OFF + 6 * B_STG_B)           // 113664
#define BIAS_OFF (RS_OFF + 512)                  // 114176
#define FUSED_SMEM (BIAS_OFF + 512)              // 114688

__global__ void __launch_bounds__(512, 1) fused_kernel(const float* __restrict__ adj,
                                                       const float* __restrict__ bias,
                                                       float* __restrict__ out) {
    extern __shared__ char sm8[];
    const uint32_t sb = smem_u32(sm8);
    float* rs = (float*)(sm8 + RS_OFF);
    float* bs = (float*)(sm8 + BIAS_OFF);

    const int tid = threadIdx.x;
    const int m0 = blockIdx.x * 128;

    if (tid < DF) bs[tid] = bias[tid];

    if (tid >= 256) {
        // ================= PRODUCERS =================
        const int ptid = tid - 256;
        const int r = ptid >> 1;           // adj row within tile
        const int hf = ptid & 1;           // 16-float half of 32-col chunk
        const float* agsrc = adj + (size_t)(m0 + r) * N_ROWS + hf * 16;
        const uint32_t a_sts = (uint32_t)r * SA2 + hf * 8;   // u32 units

        const int kk = ptid >> 4;          // pair-row (0..15)
        const int nb = ptid & 15;          // 8-u32 col block
        const uint32_t* bgsrc = g_XWp + (size_t)kk * DF + nb * 8;
        const uint32_t b_dst = sb + B_OFF + ((uint32_t)kk * SB2 + nb * 8) * 4;

        float4 a0b[4], a1b[4];
        float rsum = 0.0f;

#define LDGA(cn, BUF) do {                                                       \
            const float* _p = agsrc + (size_t)(cn) * KC;                         \
            BUF[0] = *(const float4*)(_p);                                       \
            BUF[1] = *(const float4*)(_p + 4);                                   \
            BUF[2] = *(const float4*)(_p + 8);                                   \
            BUF[3] = *(const float4*)(_p + 12);                                  \
        } while (0)
#define CPB(cn, S) do {                                                          \
            const uint32_t* _p = bgsrc + (size_t)(cn) * 16 * DF;                 \
            uint32_t _d = b_dst + (uint32_t)(S) * B_STG_B;                       \
            cp_async16(_d,      _p);                                             \
            cp_async16(_d + 16, _p + 4);                                         \
        } while (0)
#define STSA(BUF, S) do {                                                        \
            uint32_t pk[8];                                                      \
            _Pragma("unroll")                                                    \
            for (int q = 0; q < 4; q++) {                                        \
                float e0 = __expf(BUF[q].x), e1 = __expf(BUF[q].y);              \
                float e2 = __expf(BUF[q].z), e3 = __expf(BUF[q].w);              \
                rsum += (e0 + e1) + (e2 + e3);                                   \
                pk[2 * q]     = packh2(e0, e1);                                  \
                pk[2 * q + 1] = packh2(e2, e3);                                  \
            }                                                                    \
            uint32_t* As = (uint32_t*)(sm8 + A_OFF + (size_t)(S) * A_STG_B);     \
            *(uint4*)(As + a_sts)     = make_uint4(pk[0], pk[1], pk[2], pk[3]);  \
            *(uint4*)(As + a_sts + 4) = make_uint4(pk[4], pk[5], pk[6], pk[7]);  \
        } while (0)

        LDGA(0, a0b);
        LDGA(1, a1b);

        int p = 0;
        for (int pt = 0; pt < NPITER; ++pt) {
            if (pt >= NPAIR) bar_sync_named(4 + p);
            const int c0 = 2 * pt;
            // launch both B chunks of this pair as one cp group
            CPB(c0, 2 * p);
            CPB(c0 + 1, 2 * p + 1);
            CP_COMMIT();
            // exp + STS both A chunks, prefetching the next pair's adj
            STSA(a0b, 2 * p);
            if (c0 + 2 < NITER) LDGA(c0 + 2, a0b);
            STSA(a1b, 2 * p + 1);
            if (c0 + 3 < NITER) LDGA(c0 + 3, a1b);
            CP_WAIT(0);
            __threadfence_block();
            bar_arrive_named(1 + p);
            p = (p == NPAIR - 1) ? 0 : p + 1;
        }

        rsum += __shfl_xor_sync(0xffffffffu, rsum, 1);
        if (hf == 0) rs[r] = rsum;
        __syncthreads();
        // producers done (consumers do epilogue)
    } else {
        // ================= CONSUMERS =================
        const int wid = tid >> 5;
        const int lid = tid & 31;
        const int g = lid >> 2, tg = lid & 3;
        const int mB = (wid & 3) * 32;
        const int nB = (wid >> 2) * 64;

        float acc[2][8][4];
#pragma unroll
        for (int i = 0; i < 2; i++)
#pragma unroll
            for (int j = 0; j < 8; j++)
#pragma unroll
                for (int c = 0; c < 4; c++) acc[i][j][c] = 0.0f;

        int p = 0;
        for (int pt = 0; pt < NPITER; ++pt) {
            bar_sync_named(1 + p);
#pragma unroll
            for (int half = 0; half < 2; half++) {
                const int s = 2 * p + half;
                const uint32_t* As = (const uint32_t*)(sm8 + A_OFF + (size_t)s * A_STG_B);
                const uint32_t* Bs = (const uint32_t*)(sm8 + B_OFF + (size_t)s * B_STG_B);
#pragma unroll
                for (int ks = 0; ks < 2; ks++) {
                    uint32_t af[2][4];
#pragma unroll
                    for (int mi = 0; mi < 2; mi++) {
                        const uint32_t* Ar = As + (mB + mi * 16 + g) * SA2 + ks * 8 + tg;
                        af[mi][0] = Ar[0];
                        af[mi][1] = Ar[8 * SA2];
                        af[mi][2] = Ar[4];
                        af[mi][3] = Ar[8 * SA2 + 4];
                    }
#pragma unroll
                    for (int ni = 0; ni < 8; ni++) {
                        const uint32_t* Br = Bs + (ks * 8 + tg) * SB2 + nB + ni * 8 + g;
                        uint32_t b0 = Br[0];
                        uint32_t b1 = Br[4 * SB2];
#pragma unroll
                        for (int mi = 0; mi < 2; mi++) {
                            asm volatile(
                                "mma.sync.aligned.m16n8k16.row.col.f32.f16.f16.f32 "
                                "{%0,%1,%2,%3}, {%4,%5,%6,%7}, {%8,%9}, {%0,%1,%2,%3};"
                                : "+f"(acc[mi][ni][0]), "+f"(acc[mi][ni][1]),
                                  "+f"(acc[mi][ni][2]), "+f"(acc[mi][ni][3])
                                : "r"(af[mi][0]), "r"(af[mi][1]), "r"(af[mi][2]), "r"(af[mi][3]),
                                  "r"(b0), "r"(b1));
                        }
                    }
                }
            }
            bar_arrive_named(4 + p);
            p = (p == NPAIR - 1) ? 0 : p + 1;
        }

        __syncthreads();   // rowsums + bias visible

        // epilogue: divide + bias + store
#pragma unroll
        for (int mi = 0; mi < 2; mi++) {
            const int r0 = mB + mi * 16 + g;
            const int r1 = r0 + 8;
            const float inv0 = 1.0f / rs[r0];
            const float inv1 = 1.0f / rs[r1];
#pragma unroll
            for (int ni = 0; ni < 8; ni++) {
                const int c = nB + ni * 8 + 2 * tg;
                const float b0v = bs[c];
                const float b1v = bs[c + 1];
                float2 o;
                o.x = acc[mi][ni][0] * inv0 + b0v;
                o.y = acc[mi][ni][1] * inv0 + b1v;
                *(float2*)(out + (size_t)(m0 + r0) * DF + c) = o;
                o.x = acc[mi][ni][2] * inv1 + b0v;
                o.y = acc[mi][ni][3] * inv1 + b1v;
                *(float2*)(out + (size_t)(m0 + r1) * DF + c) = o;
            }
        }
    }
}

// ---------------- launcher ----------------
extern "C" void kernel_launch(void* const* d_in, const int* in_sizes, int n_in,
                              void* d_out, int out_size) {
    const float* x   = (const float*)d_in[0];
    const float* adj = (const float*)d_in[1];
    const float* W   = (const float*)d_in[2];
    const float* b   = (const float*)d_in[3];
    float* out = (float*)d_out;
    (void)in_sizes; (void)n_in; (void)out_size;

    cudaFuncSetAttribute(xw_kernel, cudaFuncAttributeMaxDynamicSharedMemorySize, XW_SMEM);
    cudaFuncSetAttribute(fused_kernel, cudaFuncAttributeMaxDynamicSharedMemorySize, FUSED_SMEM);

    xw_kernel<<<N_ROWS / 128, 256, XW_SMEM>>>(x, W);
    fused_kernel<<<N_ROWS / 128, 512, FUSED_SMEM>>>(adj, b, out);
}

// round 9
// speedup vs baseline: 2.2991x; 1.1591x over previous
#include <cuda_runtime.h>
#include <cuda_fp16.h>
#include <cstdint>

// ---------------- problem constants ----------------
#define N_ROWS 16384
#define DF     128
#define KC     32                 // K chunk per ring stage
#define NITER  (N_ROWS / KC)      // 512
#define NPITER (NITER / 2)        // 256 stage-pairs
#define NPAIR  3                  // ring = 3 pairs = 6 stages

// g_XWf: XW = x@W, fp16 pairs, fragment-plane layout per 32-k chunk (2048 u32 = 8KB):
//   chunk c, block (h,ks) = (h*2+ks)*512 u32; plane j (0..3) * 128; lane*4 + (ni&3)
//   j = jh*2 + (ni>>2), jh: 0 = b0 (pair rows ks*8+tg), 1 = b1 (pair rows ks*8+4+tg)
//   lane = 4*g + tg ; value = half2{XW[2p][n], XW[2p+1][n]}, n = h*64+ni*8+g
__device__ uint32_t g_XWf[(size_t)NITER * 2048];   // 4 MiB

__device__ __forceinline__ uint32_t packh2(float lo, float hi) {
    __half2 h = __floats2half2_rn(lo, hi);
    return *(uint32_t*)&h;
}
__device__ __forceinline__ uint32_t smem_u32(const void* p) {
    uint32_t a;
    asm("{ .reg .u64 t; cvta.to.shared.u64 t, %1; cvt.u32.u64 %0, t; }" : "=r"(a) : "l"(p));
    return a;
}
__device__ __forceinline__ void cp_async16(uint32_t dst, const void* src) {
    asm volatile("cp.async.cg.shared.global [%0], [%1], 16;" :: "r"(dst), "l"(src));
}
#define CP_COMMIT() asm volatile("cp.async.commit_group;" ::: "memory")
#define CP_WAIT(n)  asm volatile("cp.async.wait_group %0;" :: "n"(n) : "memory")

__device__ __forceinline__ void bar_sync_named(int id) {
    asm volatile("bar.sync %0, 512;" :: "r"(id) : "memory");
}
__device__ __forceinline__ void bar_arrive_named(int id) {
    asm volatile("bar.arrive %0, 512;" :: "r"(id) : "memory");
}
// barrier ids: FULL(p)=1+p (1..3), EMPTY(p)=4+p (4..6)

// ---------------- kernel 1: XW = x @ W, emitted in fragment-plane order ----------------
#define XW_SMEM ((128 * 132 + 128 * 128) * 4)

__global__ void __launch_bounds__(256) xw_kernel(const float* __restrict__ x,
                                                 const float* __restrict__ W) {
    extern __shared__ float sm_xw[];
    float* xsT = sm_xw;              // [128][132] transposed x tile
    float* Ws  = sm_xw + 128 * 132;  // [128][128]
    uint32_t* stage = (uint32_t*)sm_xw;  // 8192 u32 staging (reused after compute)
    const int tid = threadIdx.x;
    const int j0 = blockIdx.x * 128;

    for (int idx = tid; idx < 128 * 128; idx += 256) {
        int j = idx >> 7, k = idx & 127;
        xsT[k * 132 + j] = x[(size_t)(j0 + j) * DF + k];
        Ws[idx] = W[idx];
    }
    __syncthreads();

    const int tx = tid & 15, ty = tid >> 4;
    const int jb = ty * 8, db = tx * 8;
    float acc[8][8];
#pragma unroll
    for (int a = 0; a < 8; a++)
#pragma unroll
        for (int b = 0; b < 8; b++) acc[a][b] = 0.0f;

    for (int k = 0; k < 128; k++) {
        float4 a0 = *(const float4*)(xsT + k * 132 + jb);
        float4 a1 = *(const float4*)(xsT + k * 132 + jb + 4);
        float4 b0 = *(const float4*)(Ws + k * 128 + db);
        float4 b1 = *(const float4*)(Ws + k * 128 + db + 4);
        float aa[8] = {a0.x, a0.y, a0.z, a0.w, a1.x, a1.y, a1.z, a1.w};
        float bb[8] = {b0.x, b0.y, b0.z, b0.w, b1.x, b1.y, b1.z, b1.w};
#pragma unroll
        for (int jj = 0; jj < 8; jj++)
#pragma unroll
            for (int dd = 0; dd < 8; dd++) acc[jj][dd] += aa[jj] * bb[dd];
    }
    __syncthreads();   // done reading xsT/Ws; reuse as staging

    // scatter into fragment-plane staging: this CTA covers 64 pair-rows = 4 chunks
#pragma unroll
    for (int q = 0; q < 4; q++) {
        const int p_local = (jb >> 1) + q;          // 0..63
        const int c_local = p_local >> 4;           // chunk 0..3
        const int kk = p_local & 15;
        const int ks = kk >> 3, r8 = kk & 7;
        const int jh = r8 >> 2, tg = r8 & 3;
#pragma unroll
        for (int dd = 0; dd < 8; dd++) {
            const int n = db + dd;
            const int h = n >> 6, ni = (n >> 3) & 7, g = n & 7;
            const int lane = 4 * g + tg;
            const int j = jh * 2 + (ni >> 2);
            const int off = c_local * 2048 + (h * 2 + ks) * 512 + j * 128
                          + lane * 4 + (ni & 3);
            stage[off] = packh2(acc[2 * q][dd], acc[2 * q + 1][dd]);
        }
    }
    __syncthreads();

    // linear coalesced copy to global (4 chunks = 8192 u32 = 2048 uint4)
    uint4* dst = (uint4*)(g_XWf + (size_t)blockIdx.x * 8192);
    const uint4* srcv = (const uint4*)stage;
#pragma unroll
    for (int i = 0; i < 8; i++) dst[tid + i * 256] = srcv[tid + i * 256];
}

// ---------------- kernel 2: warp-specialized fused exp + softmax-GEMM ----------------
// 512 threads: tid<256 = MMA consumers (8 warps), tid>=256 = producers.
// Ring: 6 stages (3 pairs) x { A: 128x20 u32 (10240B), B: 2048 u32 (8192B) }.
#define SA2 20
#define A_STG_B  (128 * SA2 * 4)                 // 10240
#define B_STG_B  8192
#define A_OFF    0u
#define B_OFF    (A_OFF + 6 * A_STG_B)           // 61440
#define RS_OFF   (B_OFF + 6 * B_STG_B)           // 110592
#define BIAS_OFF (RS_OFF + 512)                  // 111104
#define FUSED_SMEM (BIAS_OFF + 512)              // 111616

__global__ void __launch_bounds__(512, 1) fused_kernel(const float* __restrict__ adj,
                                                       const float* __restrict__ bias,
                                                       float* __restrict__ out) {
    extern __shared__ char sm8[];
    const uint32_t sb = smem_u32(sm8);
    float* rs = (float*)(sm8 + RS_OFF);
    float* bs = (float*)(sm8 + BIAS_OFF);

    const int tid = threadIdx.x;
    const int m0 = blockIdx.x * 128;

    if (tid < DF) bs[tid] = bias[tid];

    if (tid >= 256) {
        // ================= PRODUCERS =================
        const int ptid = tid - 256;
        const int r = ptid >> 1;           // adj row within tile
        const int hf = ptid & 1;           // 16-float half of 32-col chunk
        const float* agsrc = adj + (size_t)(m0 + r) * N_ROWS + hf * 16;
        const uint32_t a_sts = (uint32_t)r * SA2 + hf * 8;   // u32 units

        // B: linear 32B per thread per chunk
        const uint32_t* bgsrc = g_XWf + (size_t)ptid * 8;
        const uint32_t b_dst = sb + B_OFF + (uint32_t)ptid * 32;

        float4 a0b[4], a1b[4];
        float rsum = 0.0f;

#define LDGA(cn, BUF) do {                                                       \
            const float* _p = agsrc + (size_t)(cn) * KC;                         \
            BUF[0] = *(const float4*)(_p);                                       \
            BUF[1] = *(const float4*)(_p + 4);                                   \
            BUF[2] = *(const float4*)(_p + 8);                                   \
            BUF[3] = *(const float4*)(_p + 12);                                  \
        } while (0)
#define CPB(cn, S) do {                                                          \
            const uint32_t* _p = bgsrc + (size_t)(cn) * 2048;                    \
            uint32_t _d = b_dst + (uint32_t)(S) * B_STG_B;                       \
            cp_async16(_d,      _p);                                             \
            cp_async16(_d + 16, _p + 4);                                         \
        } while (0)
#define STSA(BUF, S) do {                                                        \
            uint32_t pk[8];                                                      \
            _Pragma("unroll")                                                    \
            for (int q = 0; q < 4; q++) {                                        \
                float e0 = __expf(BUF[q].x), e1 = __expf(BUF[q].y);              \
                float e2 = __expf(BUF[q].z), e3 = __expf(BUF[q].w);              \
                rsum += (e0 + e1) + (e2 + e3);                                   \
                pk[2 * q]     = packh2(e0, e1);                                  \
                pk[2 * q + 1] = packh2(e2, e3);                                  \
            }                                                                    \
            uint32_t* As = (uint32_t*)(sm8 + A_OFF + (size_t)(S) * A_STG_B);     \
            *(uint4*)(As + a_sts)     = make_uint4(pk[0], pk[1], pk[2], pk[3]);  \
            *(uint4*)(As + a_sts + 4) = make_uint4(pk[4], pk[5], pk[6], pk[7]);  \
        } while (0)

        LDGA(0, a0b);
        LDGA(1, a1b);
        // prologue: B for pair 0 into slots 0,1
        CPB(0, 0);
        CPB(1, 1);
        CP_COMMIT();

        int p = 0;
        for (int pt = 0; pt < NPITER; ++pt) {
            const int pn = (p == NPAIR - 1) ? 0 : p + 1;
            // issue B for NEXT pair (one pair ahead)
            if (pt + 1 < NPITER) {
                if (pt + 1 >= NPAIR) bar_sync_named(4 + pn);   // slots 2pn,2pn+1 free
                const int c0n = 2 * (pt + 1);
                CPB(c0n, 2 * pn);
                CPB(c0n + 1, 2 * pn + 1);
                CP_COMMIT();
            }
            // exp + STS this pair's A (slots guarded by EMPTY(p), synced last body)
            const int c0 = 2 * pt;
            STSA(a0b, 2 * p);
            if (c0 + 2 < NITER) LDGA(c0 + 2, a0b);
            STSA(a1b, 2 * p + 1);
            if (c0 + 3 < NITER) LDGA(c0 + 3, a1b);
            // B of THIS pair (issued last body) must be complete; next pair in flight
            if (pt + 1 < NPITER) { CP_WAIT(1); } else { CP_WAIT(0); }
            __threadfence_block();
            bar_arrive_named(1 + p);
            p = pn;
        }

        rsum += __shfl_xor_sync(0xffffffffu, rsum, 1);
        if (hf == 0) rs[r] = rsum;
        __syncthreads();
        // producers done (consumers do epilogue)
    } else {
        // ================= CONSUMERS =================
        const int wid = tid >> 5;
        const int lid = tid & 31;
        const int g = lid >> 2, tg = lid & 3;
        const int mB = (wid & 3) * 32;
        const int h  = wid >> 2;
        const int nB = h * 64;

        float acc[2][8][4];
#pragma unroll
        for (int i = 0; i < 2; i++)
#pragma unroll
            for (int j = 0; j < 8; j++)
#pragma unroll
                for (int c = 0; c < 4; c++) acc[i][j][c] = 0.0f;

        int p = 0;
        for (int pt = 0; pt < NPITER; ++pt) {
            bar_sync_named(1 + p);
#pragma unroll
            for (int half = 0; half < 2; half++) {
                const int s = 2 * p + half;
                const uint32_t* As = (const uint32_t*)(sm8 + A_OFF + (size_t)s * A_STG_B);
                const uint32_t* Bs = (const uint32_t*)(sm8 + B_OFF + (size_t)s * B_STG_B);
#pragma unroll
                for (int ks = 0; ks < 2; ks++) {
                    uint32_t af[2][4];
#pragma unroll
                    for (int mi = 0; mi < 2; mi++) {
                        const uint32_t* Ar = As + (mB + mi * 16 + g) * SA2 + ks * 8 + tg;
                        af[mi][0] = Ar[0];
                        af[mi][1] = Ar[8 * SA2];
                        af[mi][2] = Ar[4];
                        af[mi][3] = Ar[8 * SA2 + 4];
                    }
                    // B fragments: 4 conflict-free LDS.128 from plane layout
                    const uint32_t* Bb = Bs + (h * 2 + ks) * 512 + lid * 4;
                    const uint4 q0 = *(const uint4*)(Bb);          // b0, ni 0..3
                    const uint4 q1 = *(const uint4*)(Bb + 128);    // b0, ni 4..7
                    const uint4 q2 = *(const uint4*)(Bb + 256);    // b1, ni 0..3
                    const uint4 q3 = *(const uint4*)(Bb + 384);    // b1, ni 4..7
                    const uint32_t b0a[8] = {q0.x, q0.y, q0.z, q0.w, q1.x, q1.y, q1.z, q1.w};
                    const uint32_t b1a[8] = {q2.x, q2.y, q2.z, q2.w, q3.x, q3.y, q3.z, q3.w};
#pragma unroll
                    for (int ni = 0; ni < 8; ni++) {
#pragma unroll
                        for (int mi = 0; mi < 2; mi++) {
                            asm volatile(
                                "mma.sync.aligned.m16n8k16.row.col.f32.f16.f16.f32 "
                                "{%0,%1,%2,%3}, {%4,%5,%6,%7}, {%8,%9}, {%0,%1,%2,%3};"
                                : "+f"(acc[mi][ni][0]), "+f"(acc[mi][ni][1]),
                                  "+f"(acc[mi][ni][2]), "+f"(acc[mi][ni][3])
                                : "r"(af[mi][0]), "r"(af[mi][1]), "r"(af[mi][2]), "r"(af[mi][3]),
                                  "r"(b0a[ni]), "r"(b1a[ni]));
                        }
                    }
                }
            }
            bar_arrive_named(4 + p);
            p = (p == NPAIR - 1) ? 0 : p + 1;
        }

        __syncthreads();   // rowsums + bias visible

        // epilogue: divide + bias + store
#pragma unroll
        for (int mi = 0; mi < 2; mi++) {
            const int r0 = mB + mi * 16 + g;
            const int r1 = r0 + 8;
            const float inv0 = 1.0f / rs[r0];
            const float inv1 = 1.0f / rs[r1];
#pragma unroll
            for (int ni = 0; ni < 8; ni++) {
                const int c = nB + ni * 8 + 2 * tg;
                const float b0v = bs[c];
                const float b1v = bs[c + 1];
                float2 o;
                o.x = acc[mi][ni][0] * inv0 + b0v;
                o.y = acc[mi][ni][1] * inv0 + b1v;
                *(float2*)(out + (size_t)(m0 + r0) * DF + c) = o;
                o.x = acc[mi][ni][2] * inv1 + b0v;
                o.y = acc[mi][ni][3] * inv1 + b1v;
                *(float2*)(out + (size_t)(m0 + r1) * DF + c) = o;
            }
        }
    }
}

// ---------------- launcher ----------------
extern "C" void kernel_launch(void* const* d_in, const int* in_sizes, int n_in,
                              void* d_out, int out_size) {
    const float* x   = (const float*)d_in[0];
    const float* adj = (const float*)d_in[1];
    const float* W   = (const float*)d_in[2];
    const float* b   = (const float*)d_in[3];
    float* out = (float*)d_out;
    (void)in_sizes; (void)n_in; (void)out_size;

    cudaFuncSetAttribute(xw_kernel, cudaFuncAttributeMaxDynamicSharedMemorySize, XW_SMEM);
    cudaFuncSetAttribute(fused_kernel, cudaFuncAttributeMaxDynamicSharedMemorySize, FUSED_SMEM);

    xw_kernel<<<N_ROWS / 128, 256, XW_SMEM>>>(x, W);
    fused_kernel<<<N_ROWS / 128, 512, FUSED_SMEM>>>(adj, b, out);
}